// round 15
// baseline (speedup 1.0000x reference)
#include <cuda_runtime.h>
#include <cuda_fp16.h>
#include <cstdint>
#include <math.h>

#define Bsz 1024
#define Dd  512
#define Nn  16
#define Hh  512
#define M_TOT 16384
#define KAE  512                 // A row elems (hi-only fp16)
#define KBE  512                 // B row elems
#define KS   64                  // K elems per chunk
#define NCH  8
#define ROWB 144                 // smem row stride (128B data + 16B pad)

// ---- GEMM1/2: CTA 64x128, 256 thr, 3-stage, occ 2 ----
#define TM12    64
#define SB12    (TM12 * ROWB)        // 9216
#define STG12   (SB12 + 128 * ROWB)  // 27648
#define SMEM12  (3 * STG12)          // 82944

// ---- GEMM3: CTA 128x128, 256 thr, 3-stage, jt-fused, occ 2 ----
#define TM3     128
#define STG3_A  (TM3 * ROWB)         // 18432
#define STG3    (2 * STG3_A)         // 36864
#define SMEM3   (3 * STG3)           // 110592

// ---------------- scratch ----------------
__device__ __half g_A0[(size_t)M_TOT * KAE];
__device__ __half g_A1[(size_t)M_TOT * KAE];
__device__ __half g_W1[(size_t)Dd * KBE];
__device__ __half g_W2[(size_t)Dd * KBE];
__device__ __half g_Wc[(size_t)Nn * Hh * KBE];

// ---------------- helpers ----------------
static __device__ __forceinline__ uint32_t smem_u32(const void* p) {
    uint32_t a;
    asm("{ .reg .u64 t; cvta.to.shared.u64 t, %1; cvt.u32.u64 %0, t; }" : "=r"(a) : "l"(p));
    return a;
}
static __device__ __forceinline__ float lrelu(float v) { return v >= 0.0f ? v : 0.1f * v; }

#define LDSM4(r, a)                                                                     \
    asm volatile("ldmatrix.sync.aligned.m8n8.x4.shared.b16 {%0,%1,%2,%3}, [%4];"        \
                 : "=r"((r)[0]), "=r"((r)[1]), "=r"((r)[2]), "=r"((r)[3]) : "r"(a))
#define MMA(d, a, b0, b1)                                                               \
    asm volatile("mma.sync.aligned.m16n8k16.row.col.f32.f16.f16.f32 "                   \
                 "{%0,%1,%2,%3},{%4,%5,%6,%7},{%8,%9},{%0,%1,%2,%3};"                   \
                 : "+f"((d)[0]), "+f"((d)[1]), "+f"((d)[2]), "+f"((d)[3])               \
                 : "r"((a)[0]), "r"((a)[1]), "r"((a)[2]), "r"((a)[3]), "r"(b0), "r"(b1))
#define CPA(dst, src) asm volatile("cp.async.cg.shared.global [%0], [%1], 16;" :: "r"(dst), "l"(src))
#define CPC()  asm volatile("cp.async.commit_group;" ::: "memory")
#define CPW1() asm volatile("cp.async.wait_group 1;" ::: "memory")
#define CPW0() asm volatile("cp.async.wait_group 0;" ::: "memory")

// ---------------------------------------------------------------------------
// convert x (B, D, N) fp32 -> g_A0[m = n*B + b][d] fp16
// ---------------------------------------------------------------------------
__global__ void k_convert_x(const float* __restrict__ x) {
    __shared__ float sm[Dd * 17];
    int b = blockIdx.x;
    const float4* xp = reinterpret_cast<const float4*>(x + (size_t)b * Dd * Nn);
    for (int v = threadIdx.x; v < 2048; v += blockDim.x) {
        float4 q = xp[v];
        int d = v >> 2, n0 = (v & 3) * 4;
        sm[d * 17 + n0 + 0] = q.x; sm[d * 17 + n0 + 1] = q.y;
        sm[d * 17 + n0 + 2] = q.z; sm[d * 17 + n0 + 3] = q.w;
    }
    __syncthreads();
    int d0 = (threadIdx.x & 127) * 4;
    int nh = threadIdx.x >> 7;
    for (int nb = 0; nb < Nn; nb += 2) {
        int n = nb + nh;
        __half* row = g_A0 + (size_t)(n * Bsz + b) * KAE;
        __half h[4];
#pragma unroll
        for (int e = 0; e < 4; e++) h[e] = __float2half_rn(sm[(d0 + e) * 17 + n]);
        *reinterpret_cast<uint2*>(row + d0) = *reinterpret_cast<uint2*>(h);
    }
}

// ---------------------------------------------------------------------------
// convert weights W[k][j] -> B'[j][k] fp16 transposed
// ---------------------------------------------------------------------------
__global__ void k_convert_w(const float* __restrict__ Ws1,
                            const float* __restrict__ Ws2,
                            const float* __restrict__ Wc1) {
    __shared__ float sm[32][33];
    int z = blockIdx.z;
    const float* in;
    __half* out;
    if (z == 0)      { in = Ws1; out = g_W1; }
    else if (z == 1) { in = Ws2; out = g_W2; }
    else             { in = Wc1 + (size_t)(z - 2) * Dd * Hh;
                       out = g_Wc + (size_t)(z - 2) * Hh * KBE; }
    int k0 = blockIdx.x * 32, j0 = blockIdx.y * 32;
    int tx = threadIdx.x, ty = threadIdx.y;
#pragma unroll
    for (int i = 0; i < 4; i++) {
        int r = ty + i * 8;
        sm[r][tx] = in[(size_t)(k0 + r) * Dd + j0 + tx];
    }
    __syncthreads();
#pragma unroll
    for (int i = 0; i < 4; i++) {
        int r = ty + i * 8;
        out[(size_t)(j0 + r) * KBE + k0 + tx] = __float2half_rn(sm[tx][r]);
    }
}

// ---------------------------------------------------------------------------
// GEMM1/2 (R10 config): CTA 64x128, warp 32x32, 3-stage, occ 2.
// Aout = fp16(lrelu(acc + bias))
// ---------------------------------------------------------------------------
__global__ void __launch_bounds__(256, 2)
k_g12(const __half* __restrict__ Ag,
      const __half* __restrict__ Bg,
      const float* __restrict__ bias,
      __half* __restrict__ Aout) {
    extern __shared__ char smem[];
    uint32_t sb = smem_u32(smem);
    int tid = threadIdx.x, lane = tid & 31, wid = tid >> 5;
    int wm = wid & 1, wn = wid >> 1;

    int jt = blockIdx.x;
    int m0 = blockIdx.y * TM12;
    int j0 = jt * 128;

    const __half* Ap = Ag + (size_t)m0 * KAE;
    const __half* Bp = Bg + (size_t)j0 * KBE;

    float acc[2][4][4];
#pragma unroll
    for (int a = 0; a < 2; a++)
#pragma unroll
        for (int b = 0; b < 4; b++)
#pragma unroll
            for (int c = 0; c < 4; c++) acc[a][b][c] = 0.0f;

    uint32_t a_off[2], b_off[2];
#pragma unroll
    for (int mi = 0; mi < 2; mi++)
        a_off[mi] = (uint32_t)((wm * 32 + mi * 16 + (lane & 15)) * ROWB + (lane >> 4) * 16);
#pragma unroll
    for (int p = 0; p < 2; p++)
        b_off[p] = (uint32_t)(SB12 + (wn * 32 + p * 16 + (lane & 15)) * ROWB + (lane >> 4) * 16);

#define STAGE_LOAD12(base, c)                                                           \
    do {                                                                                \
        int ko = (c) * KS;                                                              \
        _Pragma("unroll")                                                               \
        for (int i = 0; i < 2; i++) {                                                   \
            int idx = tid + i * 256, row = idx >> 3, seg = idx & 7;                     \
            CPA((base) + row * ROWB + seg * 16, Ap + (size_t)row * KAE + ko + seg * 8); \
        }                                                                               \
        _Pragma("unroll")                                                               \
        for (int i = 0; i < 4; i++) {                                                   \
            int idx = tid + i * 256, row = idx >> 3, seg = idx & 7;                     \
            CPA((base) + SB12 + row * ROWB + seg * 16,                                  \
                Bp + (size_t)row * KBE + ko + seg * 8);                                 \
        }                                                                               \
        CPC();                                                                          \
    } while (0)

    STAGE_LOAD12(sb, 0);
    STAGE_LOAD12(sb + STG12, 1);

    int sbuf = 0, wbuf = 2;
    for (int c = 0; c < NCH; c++) {
        if (c == NCH - 1) { CPW0(); } else { CPW1(); }
        __syncthreads();
        if (c + 2 < NCH) STAGE_LOAD12(sb + wbuf * STG12, c + 2);
        uint32_t base = sb + sbuf * STG12;
#pragma unroll
        for (int kk = 0; kk < 4; kk++) {
            uint32_t fa[2][4], fb[2][4];
#pragma unroll
            for (int p = 0; p < 2; p++) LDSM4(fb[p], base + b_off[p] + kk * 32);
#pragma unroll
            for (int mi = 0; mi < 2; mi++) LDSM4(fa[mi], base + a_off[mi] + kk * 32);
#pragma unroll
            for (int mi = 0; mi < 2; mi++)
#pragma unroll
                for (int p = 0; p < 2; p++) {
                    MMA(acc[mi][2 * p],     fa[mi], fb[p][0], fb[p][2]);
                    MMA(acc[mi][2 * p + 1], fa[mi], fb[p][1], fb[p][3]);
                }
        }
        sbuf = (sbuf == 2) ? 0 : sbuf + 1;
        wbuf = (wbuf == 2) ? 0 : wbuf + 1;
    }
#undef STAGE_LOAD12

#pragma unroll
    for (int mi = 0; mi < 2; mi++)
#pragma unroll
        for (int half = 0; half < 2; half++) {
            int row = m0 + wm * 32 + mi * 16 + (lane >> 2) + half * 8;
            __half* rowp = Aout + (size_t)row * KAE;
#pragma unroll
            for (int g = 0; g < 4; g++) {
                int col = j0 + wn * 32 + g * 8 + (lane & 3) * 2;
                float v0 = lrelu(acc[mi][g][half * 2]     + __ldg(&bias[col]));
                float v1 = lrelu(acc[mi][g][half * 2 + 1] + __ldg(&bias[col + 1]));
                __half hh[2] = {__float2half_rn(v0), __float2half_rn(v1)};
                *reinterpret_cast<uint32_t*>(rowp + col) = *reinterpret_cast<uint32_t*>(hh);
            }
        }
}

// ---------------------------------------------------------------------------
// GEMM3, jt-fused: CTA = (n, m-tile 128), loops jt = 0..3 as one continuous
// 32-chunk 3-stage pipeline. Folds acc -> rs at each jt boundary.
// Writes full_out directly: out[16384 + m*16 + n] = sum + bc2[n].
// ---------------------------------------------------------------------------
__global__ void __launch_bounds__(256, 2)
k_g3(const __half* __restrict__ Ag,
     const __half* __restrict__ Bg,
     const float* __restrict__ bias,
     const float* __restrict__ wc2,
     const float* __restrict__ bc2,
     float* __restrict__ out) {
    extern __shared__ char smem[];
    uint32_t sb = smem_u32(smem);
    int tid = threadIdx.x, lane = tid & 31, wid = tid >> 5;
    int wm = wid & 1, wn = wid >> 1;

    int n  = blockIdx.x;
    int m0 = blockIdx.y * TM3;

    const __half* Ap = Ag + (size_t)m0 * KAE;
    const __half* Bn = Bg + (size_t)n * Hh * KBE;

    float acc[4][4][4];
#pragma unroll
    for (int a = 0; a < 4; a++)
#pragma unroll
        for (int b = 0; b < 4; b++)
#pragma unroll
            for (int c = 0; c < 4; c++) acc[a][b][c] = 0.0f;

    float rs[4][2];
#pragma unroll
    for (int a = 0; a < 4; a++) { rs[a][0] = 0.0f; rs[a][1] = 0.0f; }

    uint32_t a_off[4], b_off[2];
#pragma unroll
    for (int mi = 0; mi < 4; mi++)
        a_off[mi] = (uint32_t)((wm * 64 + mi * 16 + (lane & 15)) * ROWB + (lane >> 4) * 16);
#pragma unroll
    for (int p = 0; p < 2; p++)
        b_off[p] = (uint32_t)(STG3_A + (wn * 32 + p * 16 + (lane & 15)) * ROWB + (lane >> 4) * 16);

    // chunk t (0..31): jt = t>>3, c = t&7. A cols c*KS; B rows jt*128, cols c*KS.
#define STAGE_LOAD3(base, t)                                                            \
    do {                                                                                \
        int ko = ((t) & 7) * KS;                                                        \
        const __half* Bp = Bn + (size_t)(((t) >> 3) * 128) * KBE;                       \
        _Pragma("unroll")                                                               \
        for (int i = 0; i < 4; i++) {                                                   \
            int idx = tid + i * 256, row = idx >> 3, seg = idx & 7;                     \
            CPA((base) + row * ROWB + seg * 16, Ap + (size_t)row * KAE + ko + seg * 8); \
        }                                                                               \
        _Pragma("unroll")                                                               \
        for (int i = 0; i < 4; i++) {                                                   \
            int idx = tid + i * 256, row = idx >> 3, seg = idx & 7;                     \
            CPA((base) + STG3_A + row * ROWB + seg * 16,                                \
                Bp + (size_t)row * KBE + ko + seg * 8);                                 \
        }                                                                               \
        CPC();                                                                          \
    } while (0)

    STAGE_LOAD3(sb, 0);
    STAGE_LOAD3(sb + STG3, 1);

    int sbuf = 0, wbuf = 2;
#pragma unroll 1
    for (int t = 0; t < 4 * NCH; t++) {
        if (t == 4 * NCH - 1) { CPW0(); } else { CPW1(); }
        __syncthreads();
        if (t + 2 < 4 * NCH) STAGE_LOAD3(sb + wbuf * STG3, t + 2);
        uint32_t base = sb + sbuf * STG3;
#pragma unroll
        for (int kk = 0; kk < 4; kk++) {
            uint32_t fa[4][4], fb[2][4];
#pragma unroll
            for (int p = 0; p < 2; p++) LDSM4(fb[p], base + b_off[p] + kk * 32);
#pragma unroll
            for (int mi = 0; mi < 4; mi++) LDSM4(fa[mi], base + a_off[mi] + kk * 32);
#pragma unroll
            for (int mi = 0; mi < 4; mi++)
#pragma unroll
                for (int p = 0; p < 2; p++) {
                    MMA(acc[mi][2 * p],     fa[mi], fb[p][0], fb[p][2]);
                    MMA(acc[mi][2 * p + 1], fa[mi], fb[p][1], fb[p][3]);
                }
        }
        if ((t & 7) == 7) {
            // fold acc into rs for this jt, then reset acc
            int jt = t >> 3;
#pragma unroll
            for (int mi = 0; mi < 4; mi++)
#pragma unroll
                for (int half = 0; half < 2; half++) {
                    float s = 0.0f;
#pragma unroll
                    for (int g = 0; g < 4; g++) {
                        int col = jt * 128 + wn * 32 + g * 8 + (lane & 3) * 2;
                        int bi = n * Hh + col;
                        s += lrelu(acc[mi][g][half * 2]     + __ldg(&bias[bi]))     * __ldg(&wc2[bi]);
                        s += lrelu(acc[mi][g][half * 2 + 1] + __ldg(&bias[bi + 1])) * __ldg(&wc2[bi + 1]);
                    }
                    rs[mi][half] += s;
                }
#pragma unroll
            for (int a = 0; a < 4; a++)
#pragma unroll
                for (int b = 0; b < 4; b++)
#pragma unroll
                    for (int e = 0; e < 4; e++) acc[a][b][e] = 0.0f;
        }
        sbuf = (sbuf == 2) ? 0 : sbuf + 1;
        wbuf = (wbuf == 2) ? 0 : wbuf + 1;
    }
#undef STAGE_LOAD3

    // reduce rs over the lane quad, then across warps via smem
#pragma unroll
    for (int mi = 0; mi < 4; mi++)
#pragma unroll
        for (int half = 0; half < 2; half++) {
            float s = rs[mi][half];
            s += __shfl_xor_sync(0xffffffffu, s, 1);
            s += __shfl_xor_sync(0xffffffffu, s, 2);
            rs[mi][half] = s;
        }
    __syncthreads();
    float* red = reinterpret_cast<float*>(smem);
    if ((lane & 3) == 0) {
#pragma unroll
        for (int mi = 0; mi < 4; mi++)
#pragma unroll
            for (int half = 0; half < 2; half++) {
                int rl = wm * 64 + mi * 16 + (lane >> 2) + half * 8;
                red[wn * 128 + rl] = rs[mi][half];
            }
    }
    __syncthreads();
    if (tid < 128) {
        float tot = red[tid] + red[128 + tid] + red[256 + tid] + red[384 + tid];
        out[16384 + (size_t)(m0 + tid) * Nn + n] = tot + bc2[n];
    }
}

// ---------------------------------------------------------------------------
// sigmoid diagonal gather: out[b*16+n] = sigmoid(full_out[(n*B+b)*16 + n])
// ---------------------------------------------------------------------------
__global__ void k_sig(float* __restrict__ out) {
    int i = blockIdx.x * blockDim.x + threadIdx.x;
    if (i >= Bsz * Nn) return;
    int b = i >> 4, n = i & 15;
    float lg = out[16384 + (size_t)(n * Bsz + b) * Nn + n];
    out[i] = 1.0f / (1.0f + expf(-lg));
}

// ---------------------------------------------------------------------------
extern "C" void kernel_launch(void* const* d_in, const int* in_sizes, int n_in,
                              void* d_out, int out_size) {
    const float* x   = (const float*)d_in[0];
    const float* Ws1 = (const float*)d_in[1];
    const float* bs1 = (const float*)d_in[2];
    const float* Ws2 = (const float*)d_in[3];
    const float* bs2 = (const float*)d_in[4];
    const float* Wc1 = (const float*)d_in[5];
    const float* bc1 = (const float*)d_in[6];
    const float* Wc2 = (const float*)d_in[7];
    const float* bc2 = (const float*)d_in[8];
    float* out = (float*)d_out;

    cudaFuncSetAttribute(k_g12, cudaFuncAttributeMaxDynamicSharedMemorySize, SMEM12);
    cudaFuncSetAttribute(k_g3,  cudaFuncAttributeMaxDynamicSharedMemorySize, SMEM3);

    __half *A0p, *A1p, *W1p, *W2p, *Wcp;
    cudaGetSymbolAddress((void**)&A0p, g_A0);
    cudaGetSymbolAddress((void**)&A1p, g_A1);
    cudaGetSymbolAddress((void**)&W1p, g_W1);
    cudaGetSymbolAddress((void**)&W2p, g_W2);
    cudaGetSymbolAddress((void**)&Wcp, g_Wc);

    k_convert_x<<<Bsz, 256>>>(x);
    k_convert_w<<<dim3(16, 16, 18), dim3(32, 8)>>>(Ws1, Ws2, Wc1);

    k_g12<<<dim3(4, 256), 256, SMEM12>>>(A0p, W1p, bs1, A1p);
    k_g12<<<dim3(4, 256), 256, SMEM12>>>(A1p, W2p, bs2, A0p);
    k_g3<<<dim3(16, 128), 256, SMEM3>>>(A0p, Wcp, bc1, Wc2, bc2, out);

    k_sig<<<(Bsz * Nn + 255) / 256, 256>>>(out);
}

// round 16
// speedup vs baseline: 1.0388x; 1.0388x over previous
#include <cuda_runtime.h>
#include <cuda_fp16.h>
#include <cstdint>
#include <math.h>

#define Bsz 1024
#define Dd  512
#define Nn  16
#define Hh  512
#define M_TOT 16384
#define KAE  512                 // A row elems (hi-only fp16)
#define KBE  512                 // B row elems
#define KS   64                  // K elems per chunk
#define NCH  8
#define ROWB 144                 // smem row stride (128B data + 16B pad)

// ---- GEMM1/2: CTA 64x128, 256 thr, 3-stage, occ 2 ----
#define TM12    64
#define SB12    (TM12 * ROWB)        // 9216
#define STG12   (SB12 + 128 * ROWB)  // 27648
#define SMEM12  (3 * STG12)          // 82944

// ---- GEMM3: CTA 128x128, 256 thr, 3-stage, occ 2 + 1KB bias/wc2 preload ----
#define TM3     128
#define STG3_A  (TM3 * ROWB)         // 18432
#define STG3    (2 * STG3_A)         // 36864
#define SM3_PRE (3 * STG3)           // 110592
#define SMEM3   (SM3_PRE + 1024)     // 111616

// ---------------- scratch ----------------
__device__ __half g_A0[(size_t)M_TOT * KAE];
__device__ __half g_A1[(size_t)M_TOT * KAE];
__device__ __half g_W1[(size_t)Dd * KBE];
__device__ __half g_W2[(size_t)Dd * KBE];
__device__ __half g_Wc[(size_t)Nn * Hh * KBE];
__device__ float  g_part[4 * (size_t)M_TOT * Nn];

// ---------------- helpers ----------------
static __device__ __forceinline__ uint32_t smem_u32(const void* p) {
    uint32_t a;
    asm("{ .reg .u64 t; cvta.to.shared.u64 t, %1; cvt.u32.u64 %0, t; }" : "=r"(a) : "l"(p));
    return a;
}
static __device__ __forceinline__ float lrelu(float v) { return v >= 0.0f ? v : 0.1f * v; }

#define LDSM4(r, a)                                                                     \
    asm volatile("ldmatrix.sync.aligned.m8n8.x4.shared.b16 {%0,%1,%2,%3}, [%4];"        \
                 : "=r"((r)[0]), "=r"((r)[1]), "=r"((r)[2]), "=r"((r)[3]) : "r"(a))
#define MMA(d, a, b0, b1)                                                               \
    asm volatile("mma.sync.aligned.m16n8k16.row.col.f32.f16.f16.f32 "                   \
                 "{%0,%1,%2,%3},{%4,%5,%6,%7},{%8,%9},{%0,%1,%2,%3};"                   \
                 : "+f"((d)[0]), "+f"((d)[1]), "+f"((d)[2]), "+f"((d)[3])               \
                 : "r"((a)[0]), "r"((a)[1]), "r"((a)[2]), "r"((a)[3]), "r"(b0), "r"(b1))
#define CPA(dst, src) asm volatile("cp.async.cg.shared.global [%0], [%1], 16;" :: "r"(dst), "l"(src))
#define CPC()  asm volatile("cp.async.commit_group;" ::: "memory")
#define CPW1() asm volatile("cp.async.wait_group 1;" ::: "memory")
#define CPW0() asm volatile("cp.async.wait_group 0;" ::: "memory")

// ---------------------------------------------------------------------------
// convert x (B, D, N) fp32 -> g_A0[m = n*B + b][d] fp16
// ---------------------------------------------------------------------------
__global__ void k_convert_x(const float* __restrict__ x) {
    __shared__ float sm[Dd * 17];
    int b = blockIdx.x;
    const float4* xp = reinterpret_cast<const float4*>(x + (size_t)b * Dd * Nn);
    for (int v = threadIdx.x; v < 2048; v += blockDim.x) {
        float4 q = xp[v];
        int d = v >> 2, n0 = (v & 3) * 4;
        sm[d * 17 + n0 + 0] = q.x; sm[d * 17 + n0 + 1] = q.y;
        sm[d * 17 + n0 + 2] = q.z; sm[d * 17 + n0 + 3] = q.w;
    }
    __syncthreads();
    int d0 = (threadIdx.x & 127) * 4;
    int nh = threadIdx.x >> 7;
    for (int nb = 0; nb < Nn; nb += 2) {
        int n = nb + nh;
        __half* row = g_A0 + (size_t)(n * Bsz + b) * KAE;
        __half h[4];
#pragma unroll
        for (int e = 0; e < 4; e++) h[e] = __float2half_rn(sm[(d0 + e) * 17 + n]);
        *reinterpret_cast<uint2*>(row + d0) = *reinterpret_cast<uint2*>(h);
    }
}

// ---------------------------------------------------------------------------
// convert weights W[k][j] -> B'[j][k] fp16 transposed
// ---------------------------------------------------------------------------
__global__ void k_convert_w(const float* __restrict__ Ws1,
                            const float* __restrict__ Ws2,
                            const float* __restrict__ Wc1) {
    __shared__ float sm[32][33];
    int z = blockIdx.z;
    const float* in;
    __half* out;
    if (z == 0)      { in = Ws1; out = g_W1; }
    else if (z == 1) { in = Ws2; out = g_W2; }
    else             { in = Wc1 + (size_t)(z - 2) * Dd * Hh;
                       out = g_Wc + (size_t)(z - 2) * Hh * KBE; }
    int k0 = blockIdx.x * 32, j0 = blockIdx.y * 32;
    int tx = threadIdx.x, ty = threadIdx.y;
#pragma unroll
    for (int i = 0; i < 4; i++) {
        int r = ty + i * 8;
        sm[r][tx] = in[(size_t)(k0 + r) * Dd + j0 + tx];
    }
    __syncthreads();
#pragma unroll
    for (int i = 0; i < 4; i++) {
        int r = ty + i * 8;
        out[(size_t)(j0 + r) * KBE + k0 + tx] = __float2half_rn(sm[tx][r]);
    }
}

// ---------------------------------------------------------------------------
// GEMM1/2 (R10 config): CTA 64x128, warp 32x32, 3-stage, occ 2.
// Aout = fp16(lrelu(acc + bias))
// ---------------------------------------------------------------------------
__global__ void __launch_bounds__(256, 2)
k_g12(const __half* __restrict__ Ag,
      const __half* __restrict__ Bg,
      const float* __restrict__ bias,
      __half* __restrict__ Aout) {
    extern __shared__ char smem[];
    uint32_t sb = smem_u32(smem);
    int tid = threadIdx.x, lane = tid & 31, wid = tid >> 5;
    int wm = wid & 1, wn = wid >> 1;

    int jt = blockIdx.x;
    int m0 = blockIdx.y * TM12;
    int j0 = jt * 128;

    const __half* Ap = Ag + (size_t)m0 * KAE;
    const __half* Bp = Bg + (size_t)j0 * KBE;

    float acc[2][4][4];
#pragma unroll
    for (int a = 0; a < 2; a++)
#pragma unroll
        for (int b = 0; b < 4; b++)
#pragma unroll
            for (int c = 0; c < 4; c++) acc[a][b][c] = 0.0f;

    uint32_t a_off[2], b_off[2];
#pragma unroll
    for (int mi = 0; mi < 2; mi++)
        a_off[mi] = (uint32_t)((wm * 32 + mi * 16 + (lane & 15)) * ROWB + (lane >> 4) * 16);
#pragma unroll
    for (int p = 0; p < 2; p++)
        b_off[p] = (uint32_t)(SB12 + (wn * 32 + p * 16 + (lane & 15)) * ROWB + (lane >> 4) * 16);

#define STAGE_LOAD12(base, c)                                                           \
    do {                                                                                \
        int ko = (c) * KS;                                                              \
        _Pragma("unroll")                                                               \
        for (int i = 0; i < 2; i++) {                                                   \
            int idx = tid + i * 256, row = idx >> 3, seg = idx & 7;                     \
            CPA((base) + row * ROWB + seg * 16, Ap + (size_t)row * KAE + ko + seg * 8); \
        }                                                                               \
        _Pragma("unroll")                                                               \
        for (int i = 0; i < 4; i++) {                                                   \
            int idx = tid + i * 256, row = idx >> 3, seg = idx & 7;                     \
            CPA((base) + SB12 + row * ROWB + seg * 16,                                  \
                Bp + (size_t)row * KBE + ko + seg * 8);                                 \
        }                                                                               \
        CPC();                                                                          \
    } while (0)

    STAGE_LOAD12(sb, 0);
    STAGE_LOAD12(sb + STG12, 1);

    int sbuf = 0, wbuf = 2;
    for (int c = 0; c < NCH; c++) {
        if (c == NCH - 1) { CPW0(); } else { CPW1(); }
        __syncthreads();
        if (c + 2 < NCH) STAGE_LOAD12(sb + wbuf * STG12, c + 2);
        uint32_t base = sb + sbuf * STG12;
#pragma unroll
        for (int kk = 0; kk < 4; kk++) {
            uint32_t fa[2][4], fb[2][4];
#pragma unroll
            for (int p = 0; p < 2; p++) LDSM4(fb[p], base + b_off[p] + kk * 32);
#pragma unroll
            for (int mi = 0; mi < 2; mi++) LDSM4(fa[mi], base + a_off[mi] + kk * 32);
#pragma unroll
            for (int mi = 0; mi < 2; mi++)
#pragma unroll
                for (int p = 0; p < 2; p++) {
                    MMA(acc[mi][2 * p],     fa[mi], fb[p][0], fb[p][2]);
                    MMA(acc[mi][2 * p + 1], fa[mi], fb[p][1], fb[p][3]);
                }
        }
        sbuf = (sbuf == 2) ? 0 : sbuf + 1;
        wbuf = (wbuf == 2) ? 0 : wbuf + 1;
    }
#undef STAGE_LOAD12

#pragma unroll
    for (int mi = 0; mi < 2; mi++)
#pragma unroll
        for (int half = 0; half < 2; half++) {
            int row = m0 + wm * 32 + mi * 16 + (lane >> 2) + half * 8;
            __half* rowp = Aout + (size_t)row * KAE;
#pragma unroll
            for (int g = 0; g < 4; g++) {
                int col = j0 + wn * 32 + g * 8 + (lane & 3) * 2;
                float v0 = lrelu(acc[mi][g][half * 2]     + __ldg(&bias[col]));
                float v1 = lrelu(acc[mi][g][half * 2 + 1] + __ldg(&bias[col + 1]));
                __half hh[2] = {__float2half_rn(v0), __float2half_rn(v1)};
                *reinterpret_cast<uint32_t*>(rowp + col) = *reinterpret_cast<uint32_t*>(hh);
            }
        }
}

// ---------------------------------------------------------------------------
// GEMM3 (R10 config + smem bias/wc2 preload): CTA 128x128, warp 64x32,
// 3-stage, occ 2. K = 512.
// g_part[jt][m][n] = sum_h lrelu(acc + bc1[n,h]) * Wc2[n,h]
// ---------------------------------------------------------------------------
__global__ void __launch_bounds__(256, 2)
k_g3(const __half* __restrict__ Ag,
     const __half* __restrict__ Bg,
     const float* __restrict__ bias,
     const float* __restrict__ wc2) {
    extern __shared__ char smem[];
    uint32_t sb = smem_u32(smem);
    int tid = threadIdx.x, lane = tid & 31, wid = tid >> 5;
    int wm = wid & 1, wn = wid >> 1;

    int jt = blockIdx.x;
    int n  = blockIdx.y;
    int m0 = blockIdx.z * TM3;
    int j0 = jt * 128;

    const __half* Ap = Ag + (size_t)m0 * KAE;
    const __half* Bp = Bg + ((size_t)n * Hh + j0) * KBE;

    // preload bias/wc2 slices for this (n, jt) into smem (1 KB)
    {
        float* pre = reinterpret_cast<float*>(smem + SM3_PRE);
        if (tid < 128) {
            pre[tid]       = bias[n * Hh + j0 + tid];
            pre[128 + tid] = wc2[n * Hh + j0 + tid];
        }
    }

    float acc[4][4][4];
#pragma unroll
    for (int a = 0; a < 4; a++)
#pragma unroll
        for (int b = 0; b < 4; b++)
#pragma unroll
            for (int c = 0; c < 4; c++) acc[a][b][c] = 0.0f;

    uint32_t a_off[4], b_off[2];
#pragma unroll
    for (int mi = 0; mi < 4; mi++)
        a_off[mi] = (uint32_t)((wm * 64 + mi * 16 + (lane & 15)) * ROWB + (lane >> 4) * 16);
#pragma unroll
    for (int p = 0; p < 2; p++)
        b_off[p] = (uint32_t)(STG3_A + (wn * 32 + p * 16 + (lane & 15)) * ROWB + (lane >> 4) * 16);

#define STAGE_LOAD3(base, c)                                                            \
    do {                                                                                \
        int ko = (c) * KS;                                                              \
        _Pragma("unroll")                                                               \
        for (int i = 0; i < 4; i++) {                                                   \
            int idx = tid + i * 256, row = idx >> 3, seg = idx & 7;                     \
            CPA((base) + row * ROWB + seg * 16, Ap + (size_t)row * KAE + ko + seg * 8); \
        }                                                                               \
        _Pragma("unroll")                                                               \
        for (int i = 0; i < 4; i++) {                                                   \
            int idx = tid + i * 256, row = idx >> 3, seg = idx & 7;                     \
            CPA((base) + STG3_A + row * ROWB + seg * 16,                                \
                Bp + (size_t)row * KBE + ko + seg * 8);                                 \
        }                                                                               \
        CPC();                                                                          \
    } while (0)

    STAGE_LOAD3(sb, 0);
    STAGE_LOAD3(sb + STG3, 1);

    int sbuf = 0, wbuf = 2;
    for (int c = 0; c < NCH; c++) {
        if (c == NCH - 1) { CPW0(); } else { CPW1(); }
        __syncthreads();
        if (c + 2 < NCH) STAGE_LOAD3(sb + wbuf * STG3, c + 2);
        uint32_t base = sb + sbuf * STG3;
#pragma unroll
        for (int kk = 0; kk < 4; kk++) {
            uint32_t fa[4][4], fb[2][4];
#pragma unroll
            for (int p = 0; p < 2; p++) LDSM4(fb[p], base + b_off[p] + kk * 32);
#pragma unroll
            for (int mi = 0; mi < 4; mi++) LDSM4(fa[mi], base + a_off[mi] + kk * 32);
#pragma unroll
            for (int mi = 0; mi < 4; mi++)
#pragma unroll
                for (int p = 0; p < 2; p++) {
                    MMA(acc[mi][2 * p],     fa[mi], fb[p][0], fb[p][2]);
                    MMA(acc[mi][2 * p + 1], fa[mi], fb[p][1], fb[p][3]);
                }
        }
        sbuf = (sbuf == 2) ? 0 : sbuf + 1;
        wbuf = (wbuf == 2) ? 0 : wbuf + 1;
    }
#undef STAGE_LOAD3

    const float* pre = reinterpret_cast<const float*>(smem + SM3_PRE);
    float rs[4][2];
#pragma unroll
    for (int mi = 0; mi < 4; mi++)
#pragma unroll
        for (int half = 0; half < 2; half++) {
            float s = 0.0f;
#pragma unroll
            for (int g = 0; g < 4; g++) {
                int jc = wn * 32 + g * 8 + (lane & 3) * 2;
                s += lrelu(acc[mi][g][half * 2]     + pre[jc])     * pre[128 + jc];
                s += lrelu(acc[mi][g][half * 2 + 1] + pre[jc + 1]) * pre[128 + jc + 1];
            }
            s += __shfl_xor_sync(0xffffffffu, s, 1);
            s += __shfl_xor_sync(0xffffffffu, s, 2);
            rs[mi][half] = s;
        }
    __syncthreads();
    float* red = reinterpret_cast<float*>(smem);
    if ((lane & 3) == 0) {
#pragma unroll
        for (int mi = 0; mi < 4; mi++)
#pragma unroll
            for (int half = 0; half < 2; half++) {
                int rl = wm * 64 + mi * 16 + (lane >> 2) + half * 8;
                red[wn * 128 + rl] = rs[mi][half];
            }
    }
    __syncthreads();
    if (tid < 128) {
        float tot = red[tid] + red[128 + tid] + red[256 + tid] + red[384 + tid];
        g_part[((size_t)jt * M_TOT + m0 + tid) * Nn + n] = tot;
    }
}

// ---------------------------------------------------------------------------
// finalize (vectorized): full_out = sum parts + bc2 ; diag sigmoid (fused)
// ---------------------------------------------------------------------------
__global__ void k_fin(const float* __restrict__ bc2, float* __restrict__ out) {
    int v = blockIdx.x * blockDim.x + threadIdx.x;
    if (v >= M_TOT * Nn / 4) return;
    int i = v * 4;
    float4 a = *reinterpret_cast<const float4*>(g_part + i);
    float4 b = *reinterpret_cast<const float4*>(g_part + 262144 + i);
    float4 c = *reinterpret_cast<const float4*>(g_part + 2 * 262144 + i);
    float4 d = *reinterpret_cast<const float4*>(g_part + 3 * 262144 + i);
    int nn0 = i & 15;                  // i % 4 == 0 -> nn0 <= 12
    float4 r;
    r.x = a.x + b.x + c.x + d.x + bc2[nn0];
    r.y = a.y + b.y + c.y + d.y + bc2[nn0 + 1];
    r.z = a.z + b.z + c.z + d.z + bc2[nn0 + 2];
    r.w = a.w + b.w + c.w + d.w + bc2[nn0 + 3];
    *reinterpret_cast<float4*>(out + 16384 + i) = r;
    if (i < Bsz * Nn) {
#pragma unroll
        for (int e = 0; e < 4; e++) {
            int ii = i + e;
            int bb = ii >> 4, nn = ii & 15;
            size_t idx = ((size_t)nn * Bsz + bb) * Nn + nn;
            float lg = g_part[idx] + g_part[262144 + idx] + g_part[2 * 262144 + idx]
                     + g_part[3 * 262144 + idx] + bc2[nn];
            out[ii] = 1.0f / (1.0f + expf(-lg));
        }
    }
}

// ---------------------------------------------------------------------------
extern "C" void kernel_launch(void* const* d_in, const int* in_sizes, int n_in,
                              void* d_out, int out_size) {
    const float* x   = (const float*)d_in[0];
    const float* Ws1 = (const float*)d_in[1];
    const float* bs1 = (const float*)d_in[2];
    const float* Ws2 = (const float*)d_in[3];
    const float* bs2 = (const float*)d_in[4];
    const float* Wc1 = (const float*)d_in[5];
    const float* bc1 = (const float*)d_in[6];
    const float* Wc2 = (const float*)d_in[7];
    const float* bc2 = (const float*)d_in[8];
    float* out = (float*)d_out;

    cudaFuncSetAttribute(k_g12, cudaFuncAttributeMaxDynamicSharedMemorySize, SMEM12);
    cudaFuncSetAttribute(k_g3,  cudaFuncAttributeMaxDynamicSharedMemorySize, SMEM3);

    __half *A0p, *A1p, *W1p, *W2p, *Wcp;
    cudaGetSymbolAddress((void**)&A0p, g_A0);
    cudaGetSymbolAddress((void**)&A1p, g_A1);
    cudaGetSymbolAddress((void**)&W1p, g_W1);
    cudaGetSymbolAddress((void**)&W2p, g_W2);
    cudaGetSymbolAddress((void**)&Wcp, g_Wc);

    k_convert_x<<<Bsz, 256>>>(x);
    k_convert_w<<<dim3(16, 16, 18), dim3(32, 8)>>>(Ws1, Ws2, Wc1);

    k_g12<<<dim3(4, 256), 256, SMEM12>>>(A0p, W1p, bs1, A1p);
    k_g12<<<dim3(4, 256), 256, SMEM12>>>(A1p, W2p, bs2, A0p);
    k_g3<<<dim3(4, 16, 128), 256, SMEM3>>>(A0p, Wcp, bc1, Wc2);

    k_fin<<<(M_TOT * Nn / 4 + 255) / 256, 256>>>(bc2, out);
}